// round 14
// baseline (speedup 1.0000x reference)
#include <cuda_runtime.h>

// Batched 512-point complex forward DFT (== reference complex matmul by
// W[h,j] = exp(-2*pi*i*j*h/512)), computed as a radix-8^3 FFT.
//
// R10 (on the R8/R9 FPB=1 / 64-thread / 28-CTA operating point):
//  - double-buffered exchange with XOR-swizzled 512-entry buffers (4 KB each,
//    8 KB total = same smem granule as before -> occupancy unchanged) which
//    removes the middle "reads-done-before-reuse" __syncthreads: 3 -> 2
//    barriers per FFT. All four smem access phases verified conflict-free.

#define NROWS 32768
#define TPF 64             // threads per FFT == block size
#define BLOCK TPF

__device__ __forceinline__ float2 cadd(float2 a, float2 b) { return make_float2(a.x + b.x, a.y + b.y); }
__device__ __forceinline__ float2 csub(float2 a, float2 b) { return make_float2(a.x - b.x, a.y - b.y); }
__device__ __forceinline__ float2 cmul(float2 a, float2 b) {
    return make_float2(fmaf(a.x, b.x, -a.y * b.y), fmaf(a.x, b.y, a.y * b.x));
}
__device__ __forceinline__ float2 mul_mi(float2 a) { return make_float2(a.y, -a.x); }  // *(-i)

// 8-point DFT: A[k] = sum_j a[j] * W8^(jk),  W8 = exp(-2*pi*i/8)
__device__ __forceinline__ void dft8(const float2* a, float2* A) {
    float2 e0p = cadd(a[0], a[4]), e0m = csub(a[0], a[4]);
    float2 e1p = cadd(a[2], a[6]), e1m = csub(a[2], a[6]);
    float2 E0 = cadd(e0p, e1p), E2 = csub(e0p, e1p);
    float2 mie = mul_mi(e1m);
    float2 E1 = cadd(e0m, mie);
    float2 E3 = csub(e0m, mie);

    float2 o0p = cadd(a[1], a[5]), o0m = csub(a[1], a[5]);
    float2 o1p = cadd(a[3], a[7]), o1m = csub(a[3], a[7]);
    float2 O0 = cadd(o0p, o1p), O2 = csub(o0p, o1p);
    float2 mio = mul_mi(o1m);
    float2 O1 = cadd(o0m, mio);
    float2 O3 = csub(o0m, mio);

    const float c = 0.70710678118654752440f;  // sqrt(2)/2
    float2 t0 = O0;
    float2 t1 = make_float2(c * (O1.x + O1.y), c * (O1.y - O1.x));   // (c,-c)*O1
    float2 t2 = mul_mi(O2);                                          // (0,-1)*O2
    float2 t3 = make_float2(c * (O3.y - O3.x), -c * (O3.x + O3.y));  // (-c,-c)*O3

    A[0] = cadd(E0, t0); A[4] = csub(E0, t0);
    A[1] = cadd(E1, t1); A[5] = csub(E1, t1);
    A[2] = cadd(E2, t2); A[6] = csub(E2, t2);
    A[3] = cadd(E3, t3); A[7] = csub(E3, t3);
}

// Apply A[h] *= wb^h for h=1..7 with a depth-3 power tree.
__device__ __forceinline__ void apply_twiddles(float2* A, float2 wb) {
    float2 w2 = cmul(wb, wb);
    A[1] = cmul(A[1], wb);
    float2 w3 = cmul(w2, wb);
    float2 w4 = cmul(w2, w2);
    A[2] = cmul(A[2], w2);
    A[3] = cmul(A[3], w3);
    A[4] = cmul(A[4], w4);
    float2 w5 = cmul(w4, wb);
    float2 w6 = cmul(w4, w2);
    float2 w7 = cmul(w4, w3);
    A[5] = cmul(A[5], w5);
    A[6] = cmul(A[6], w6);
    A[7] = cmul(A[7], w7);
}

__global__ __launch_bounds__(BLOCK, 28)
void fft512_kernel(const float* __restrict__ xre, const float* __restrict__ xim,
                   const float* __restrict__ wre, const float* __restrict__ wim,
                   float* __restrict__ out) {
    __shared__ float2 bufA[512];   // stage-1 -> stage-2 exchange (4 KB)
    __shared__ float2 bufB[512];   // stage-2 -> stage-3 exchange (4 KB)

    const int t = threadIdx.x;    // thread within FFT (0..63)
    const int h0s = t >> 3;       // stage-2 digit h0
    const int j1a = t & 7;        // stage-2 digit j1a
    const size_t row = (size_t)blockIdx.x;

    // Per-thread exact base twiddles from w table row 1 (L2-resident):
    //   wb1 = W512^t, wb2 = W512^(8*j1a)
    const float2 wb1 = make_float2(wre[512 + t], wim[512 + t]);
    const float2 wb2 = make_float2(wre[512 + 8 * j1a], wim[512 + 8 * j1a]);

    const float* xr = xre + row * 512;
    const float* xi = xim + row * 512;

    float2 a[8], A[8];
    // Stage 1 input: a[j2] = x[t + 64*j2]   (coalesced 128B/warp per j2)
    #pragma unroll
    for (int j2 = 0; j2 < 8; j2++)
        a[j2] = make_float2(__ldcs(xr + t + 64 * j2), __ldcs(xi + t + 64 * j2));

    // ---- Stage 1: DFT8 over j2 -> digit h0; twiddle W512^(t*h0);
    //      bufA[8*t + (h0 ^ s(t))], s(t) = (t&7)^(t>>3)  (conflict-free) ----
    dft8(a, A);
    apply_twiddles(A, wb1);
    {
        const int st = (t & 7) ^ (t >> 3);
        #pragma unroll
        for (int h0 = 0; h0 < 8; h0++)
            bufA[8 * t + (h0 ^ st)] = A[h0];
    }
    __syncthreads();

    // ---- Stage 2: thread (h0s, j1a); DFT8 over j1b -> h10.
    //      Reads bufA (swizzle s(j1a+8*j1b) = j1a^j1b); writes bufB
    //      [64*j1a + ((8*h10+h0s) ^ 9*j1a)]. No barrier between read and
    //      write: disjoint buffers. ----
    #pragma unroll
    for (int j1b = 0; j1b < 8; j1b++)
        a[j1b] = bufA[8 * (j1a + 8 * j1b) + (h0s ^ j1a ^ j1b)];

    dft8(a, A);
    apply_twiddles(A, wb2);
    {
        const int base2 = 64 * j1a + (h0s ^ j1a);
        #pragma unroll
        for (int h10 = 0; h10 < 8; h10++)
            bufB[base2 + 8 * (h10 ^ j1a)] = A[h10];
    }
    __syncthreads();

    // ---- Stage 3: thread t owns (h0 = t&7, h10 = t>>3); logical column
    //      8*h10 + h0 == t; physical column t ^ 9*j per row j. ----
    {
        const int tl = t & 7, th = t >> 3;
        #pragma unroll
        for (int j = 0; j < 8; j++)
            a[j] = bufB[64 * j + 8 * (th ^ j) + (tl ^ j)];
    }

    dft8(a, A);

    // h = t + 64*h11: 256B contiguous per warp per store
    float2* o2 = reinterpret_cast<float2*>(out) + row * 512;
    #pragma unroll
    for (int h11 = 0; h11 < 8; h11++)
        __stcs(o2 + t + 64 * h11, A[h11]);
}

extern "C" void kernel_launch(void* const* d_in, const int* in_sizes, int n_in,
                              void* d_out, int out_size) {
    const float* x_re = (const float*)d_in[0];
    const float* x_im = (const float*)d_in[1];
    const float* w_re = (const float*)d_in[2];
    const float* w_im = (const float*)d_in[3];
    float* out = (float*)d_out;

    dim3 grid(NROWS);     // 32768 blocks, one FFT each
    dim3 block(BLOCK);    // 64 threads
    fft512_kernel<<<grid, block>>>(x_re, x_im, w_re, w_im, out);
}